// round 16
// baseline (speedup 1.0000x reference)
#include <cuda_runtime.h>
#include <cuda_bf16.h>
#include <mma.h>
#include <cstdint>

using namespace nvcuda;

#define B_   4
#define CIN  128
#define COUT 128
#define H_   128
#define W_   128
#define G_   4
#define CG   32
#define KK   9
#define HW   (H_*W_)
#define NOFF 72   // G*KK*2
#define NTILE 36  // G*KK
#define KDIM 96   // split-K per tile: 32 w_hi|s_hi + 32 w_hi|s_lo + 32 w_lo|s_hi
#define ASTR 104  // A smem ldm (bf16 elems): 208B rows, 16B-aligned
#define BSTR 136  // B smem ldm (bf16 elems): 272B rows, 16B-aligned

// ---- scratch (device globals; no allocations allowed) ----
__device__ float g_off[B_*NOFF*HW];                          // 18 MB offset map [b][o][h][w]
__device__ __align__(16) float g_xt[B_*HW*CIN];              // 33.5 MB: x transposed to NHWC
__device__ __align__(16) __nv_bfloat16 g_wA[NTILE*128*KDIM]; // 884 KB: A tiles [gk][co][k]

// ============================================================
// Kernel 0: transpose x NCHW -> NHWC ([b][hw][c], c contiguous)
// ============================================================
__global__ __launch_bounds__(256) void transpose_x(const float* __restrict__ x) {
    __shared__ float ts[32][33];
    int b = blockIdx.z, c0 = blockIdx.y * 32, p0 = blockIdx.x * 32;
    int t = threadIdx.x, lane = t & 31, w8 = t >> 5;

    #pragma unroll
    for (int i = w8; i < 32; i += 8)
        ts[i][lane] = x[((size_t)b*CIN + (c0 + i))*HW + p0 + lane];
    __syncthreads();
    #pragma unroll
    for (int j = w8; j < 32; j += 8)
        g_xt[((size_t)b*HW + p0 + j)*CIN + c0 + lane] = ts[lane][j];
}

// ============================================================
// Kernel 1: build A weight tiles [gk][co][k], k in [0,96):
//   k  0-31: w_hi(c=k)     (pairs with s_hi)
//   k 32-63: w_hi(c=k-32)  (pairs with s_lo)
//   k 64-95: w_lo(c=k-64)  (pairs with s_hi)
// ============================================================
__global__ void prep_w(const float* __restrict__ w_def) {
    int i = blockIdx.x * 256 + threadIdx.x;      // over 36*128*96
    if (i >= NTILE * 128 * KDIM) return;
    int k  = i % KDIM;
    int co = (i / KDIM) & 127;
    int gk = i / (KDIM * 128);
    int g = gk / 9, kk = gk % 9;
    int c = k & 31;

    float w = w_def[(co * CIN + g * CG + c) * KK + kk];
    __nv_bfloat16 hi = __float2bfloat16(w);
    __nv_bfloat16 v = (k < 64) ? hi : __float2bfloat16(w - __bfloat162float(hi));
    g_wA[i] = v;
}

// ============================================================
// Kernel 2: 1x1 offset conv; x staged from NHWC (contiguous rows)
// ============================================================
__global__ __launch_bounds__(256) void off_kernel(
        const float* __restrict__ w_off,
        const float* __restrict__ b_off) {
    __shared__ __align__(16) float xs[32][132];   // [px][c], 528B rows
    __shared__ __align__(16) float ws[NOFF][32];

    int b = blockIdx.z, h = blockIdx.y, w0 = blockIdx.x * 32;
    int t = threadIdx.x, lane = t & 31, wid = t >> 5;

    // NHWC staging: 32 px x 128 c, fully coalesced
    const float* xp = g_xt + ((size_t)b*HW + h*W_ + w0)*CIN;
    for (int i = t; i < 32*128; i += 256) {
        int px = i >> 7, c = i & 127;
        xs[px][c] = xp[(size_t)px*CIN + c];
    }

    float acc[9];
    #pragma unroll
    for (int j = 0; j < 9; j++) acc[j] = 0.f;
    int obase = wid * 9;

    for (int cc = 0; cc < 4; cc++) {
        __syncthreads();
        for (int i = t; i < NOFF*32; i += 256) {
            int o = i >> 5, c2 = i & 31;
            ws[o][c2] = w_off[o*CIN + cc*32 + c2];
        }
        __syncthreads();
        #pragma unroll
        for (int c2 = 0; c2 < 32; c2 += 4) {
            float4 xv = *(const float4*)&xs[lane][cc*32 + c2];
            #pragma unroll
            for (int j = 0; j < 9; j++) {
                float4 wq = *(const float4*)&ws[obase + j][c2];
                acc[j] += xv.x*wq.x + xv.y*wq.y + xv.z*wq.z + xv.w*wq.w;
            }
        }
    }
    float* op = g_off + (size_t)b*NOFF*HW + h*W_ + w0 + lane;
    #pragma unroll
    for (int j = 0; j < 9; j++)
        op[(size_t)(obase + j)*HW] = acc[j] + b_off[obase + j];
}

// ---- gather: NHWC bilinear sample -> bf16 hi/lo split into B smem ----
// 16 channels/thread as 4 float4 per corner: 16 LDG.128 total
__device__ __forceinline__ void gather_b(int gk, int h, int px, int cbase,
                                         const float* xtb, const float* offp,
                                         __nv_bfloat16* BsD) {
    int g = gk / 9, kk = gk % 9;
    float offy = offp[(size_t)(gk*2 + 0)*HW];
    float offx = offp[(size_t)(gk*2 + 1)*HW];
    int ky = kk / 3, kx = kk % 3;
    float py  = offy + (float)(ky - 1) + (float)h;
    float pxf = offx + (float)(kx - 1) + (float)px;
    float y0f = floorf(py), x0f = floorf(pxf);
    float wy1 = py - y0f, wx1 = pxf - x0f;
    float wy0 = 1.f - wy1, wx0 = 1.f - wx1;
    int y0 = (int)y0f, x0 = (int)x0f;
    int y1 = y0 + 1, x1 = x0 + 1;
    bool vy0 = (y0 >= 0) & (y0 < H_);
    bool vy1 = (y1 >= 0) & (y1 < H_);
    bool vx0 = (x0 >= 0) & (x0 < W_);
    bool vx1 = (x1 >= 0) & (x1 < W_);
    float c00 = (vy0 & vx0) ? wy0*wx0 : 0.f;
    float c01 = (vy0 & vx1) ? wy0*wx1 : 0.f;
    float c10 = (vy1 & vx0) ? wy1*wx0 : 0.f;
    float c11 = (vy1 & vx1) ? wy1*wx1 : 0.f;
    int iy0 = min(max(y0, 0), H_-1), iy1 = min(max(y1, 0), H_-1);
    int ix0 = min(max(x0, 0), W_-1), ix1 = min(max(x1, 0), W_-1);
    const float* pc = xtb + g*CG + cbase;
    const float* p00 = pc + (size_t)(iy0*W_ + ix0)*CIN;
    const float* p01 = pc + (size_t)(iy0*W_ + ix1)*CIN;
    const float* p10 = pc + (size_t)(iy1*W_ + ix0)*CIN;
    const float* p11 = pc + (size_t)(iy1*W_ + ix1)*CIN;

    #pragma unroll
    for (int q = 0; q < 4; q++) {
        float4 a = *(const float4*)(p00 + q*4);
        float4 bq = *(const float4*)(p01 + q*4);
        float4 cq = *(const float4*)(p10 + q*4);
        float4 dq = *(const float4*)(p11 + q*4);
        float vv[4];
        vv[0] = c00*a.x + c01*bq.x + c10*cq.x + c11*dq.x;
        vv[1] = c00*a.y + c01*bq.y + c10*cq.y + c11*dq.y;
        vv[2] = c00*a.z + c01*bq.z + c10*cq.z + c11*dq.z;
        vv[3] = c00*a.w + c01*bq.w + c10*cq.w + c11*dq.w;
        #pragma unroll
        for (int j = 0; j < 4; j++) {
            int c = cbase + q*4 + j;
            __nv_bfloat16 hb = __float2bfloat16(vv[j]);
            __nv_bfloat16 lb = __float2bfloat16(vv[j] - __bfloat162float(hb));
            BsD[c*BSTR + px] = hb;          // s_hi rows [0,32)
            BsD[(32 + c)*BSTR + px] = lb;   // s_lo rows [32,64)
        }
    }
}

// ============================================================
// Kernel 3: deformable conv + ReLU via WMMA bf16 split-MMA
// EXACT R11 structure (best known schedule, 396us):
// block 256 thr (8 warps), tile = 1 row (128 px) x 128 cout
// warp tile: 64 co x 32 px = 4x2 wmma 16x16x16 tiles
// single A+B smem buffers, occ 2, 2 barriers/iter.
// Only the gather internals changed (NHWC float4 loads).
// ============================================================
__global__ __launch_bounds__(256, 2) void main_kernel(float* __restrict__ out) {
    __shared__ __align__(16) __nv_bfloat16 As[128 * ASTR];  // 26624 B
    __shared__ __align__(16) __nv_bfloat16 Bs[64 * BSTR];   // 17408 B

    int t = threadIdx.x, lane = t & 31, wid = t >> 5;
    int h = blockIdx.x, b = blockIdx.y;

    // warp tiling
    int co_base = (wid & 1) * 64;     // co half
    int npx0 = (wid >> 1) * 32;       // 32-px strip

    // gather mapping
    int px = (wid & 3) * 32 + lane;   // 0..127
    int cbase = (wid >> 2) * 16;      // 0 or 16

    wmma::fragment<wmma::accumulator, 16, 16, 16, float> acc[4][2];
    #pragma unroll
    for (int mt = 0; mt < 4; mt++)
        #pragma unroll
        for (int nt = 0; nt < 2; nt++)
            wmma::fill_fragment(acc[mt][nt], 0.f);

    const float* xtb = g_xt + (size_t)b*HW*CIN;
    const float* offp = g_off + (size_t)b*NOFF*HW + h*W_ + px;

    for (int gk = 0; gk < NTILE; gk++) {
        __syncthreads();   // previous iteration's fragment loads complete

        // ---- stage A tile: [128 co][96 k] -> padded rows ----
        {
            const float4* src = (const float4*)(g_wA + (size_t)gk * (128*KDIM));
            for (int i = t; i < 1536; i += 256) {
                int row = i / 12, q = i - row * 12;
                *(float4*)((char*)As + row * (ASTR*2) + q * 16) = src[i];
            }
        }

        // ---- gather B tile (NHWC, float4 corner loads) ----
        gather_b(gk, h, px, cbase, xtb, offp, Bs);
        __syncthreads();

        // ---- 6 k16-steps; steps 4,5 reuse s_hi rows against w_lo cols ----
        #pragma unroll
        for (int kb = 0; kb < 6; kb++) {
            int krow = (kb & 3) * 16;      // 0,16,32,48,0,16
            wmma::fragment<wmma::matrix_b, 16, 16, 16, __nv_bfloat16, wmma::row_major> bf[2];
            #pragma unroll
            for (int nt = 0; nt < 2; nt++)
                wmma::load_matrix_sync(bf[nt], Bs + krow*BSTR + npx0 + nt*16, BSTR);
            #pragma unroll
            for (int mt = 0; mt < 4; mt++) {
                wmma::fragment<wmma::matrix_a, 16, 16, 16, __nv_bfloat16, wmma::row_major> af;
                wmma::load_matrix_sync(af, As + (co_base + mt*16)*ASTR + kb*16, ASTR);
                #pragma unroll
                for (int nt = 0; nt < 2; nt++)
                    wmma::mma_sync(acc[mt][nt], af, bf[nt], acc[mt][nt]);
            }
        }
    }

    // ---- epilogue: fragment ReLU + direct wmma store to gmem ----
    float* outp = out + (size_t)b*COUT*HW + h*W_;
    #pragma unroll
    for (int mt = 0; mt < 4; mt++)
        #pragma unroll
        for (int nt = 0; nt < 2; nt++) {
            #pragma unroll
            for (int e = 0; e < acc[mt][nt].num_elements; e++)
                acc[mt][nt].x[e] = fmaxf(acc[mt][nt].x[e], 0.f);
            wmma::store_matrix_sync(outp + (size_t)(co_base + mt*16)*HW + npx0 + nt*16,
                                    acc[mt][nt], HW, wmma::mem_row_major);
        }
}

// ============================================================
extern "C" void kernel_launch(void* const* d_in, const int* in_sizes, int n_in,
                              void* d_out, int out_size) {
    const float* x     = (const float*)d_in[0];
    const float* w_off = (const float*)d_in[1];
    const float* b_off = (const float*)d_in[2];
    const float* w_def = (const float*)d_in[3];
    float* out = (float*)d_out;

    transpose_x<<<dim3(HW/32, CIN/32, B_), 256>>>(x);
    prep_w<<<(NTILE*128*KDIM + 255)/256, 256>>>(w_def);
    off_kernel<<<dim3(W_/32, H_, B_), 256>>>(w_off, b_off);
    main_kernel<<<dim3(H_, B_), 256>>>(out);
}

// round 17
// speedup vs baseline: 1.5416x; 1.5416x over previous
#include <cuda_runtime.h>
#include <cuda_bf16.h>
#include <cuda_pipeline.h>
#include <mma.h>
#include <cstdint>

using namespace nvcuda;

#define B_   4
#define CIN  128
#define COUT 128
#define H_   128
#define W_   128
#define G_   4
#define CG   32
#define KK   9
#define HW   (H_*W_)
#define NOFF 72   // G*KK*2
#define NTILE 36  // G*KK
#define KDIM 96   // split-K per tile: 32 w_hi|s_hi + 32 w_hi|s_lo + 32 w_lo|s_hi
#define ASTR 104  // A smem ldm (bf16 elems): 208B rows, 16B-aligned
#define BSTR 136  // B smem ldm (bf16 elems): 272B rows, 16B-aligned

#define AS_BYTES (128 * ASTR * 2)          // 26624
#define BS_BYTES (64 * BSTR * 2)           // 17408
#define SM_TOT   (2*AS_BYTES + BS_BYTES)   // 70656 -> 2 CTAs/SM (141KB < 228KB)

// ---- scratch (device globals; no allocations allowed) ----
__device__ float g_off[B_*NOFF*HW];                          // 18 MB offset map [b][o][h][w]
__device__ __align__(16) __nv_bfloat16 g_wA[NTILE*128*KDIM]; // 884 KB: A tiles [gk][co][k]

// ============================================================
// Kernel 1: build A weight tiles [gk][co][k], k in [0,96):
//   k  0-31: w_hi(c=k)     (pairs with s_hi)
//   k 32-63: w_hi(c=k-32)  (pairs with s_lo)
//   k 64-95: w_lo(c=k-64)  (pairs with s_hi)
// ============================================================
__global__ void prep_w(const float* __restrict__ w_def) {
    int i = blockIdx.x * 256 + threadIdx.x;      // over 36*128*96
    if (i >= NTILE * 128 * KDIM) return;
    int k  = i % KDIM;
    int co = (i / KDIM) & 127;
    int gk = i / (KDIM * 128);
    int g = gk / 9, kk = gk % 9;
    int c = k & 31;

    float w = w_def[(co * CIN + g * CG + c) * KK + kk];
    __nv_bfloat16 hi = __float2bfloat16(w);
    __nv_bfloat16 v = (k < 64) ? hi : __float2bfloat16(w - __bfloat162float(hi));
    g_wA[i] = v;
}

// ============================================================
// Kernel 2: 1x1 offset conv (fp32 path; R11 known-good form)
// ============================================================
__global__ __launch_bounds__(256) void off_kernel(
        const float* __restrict__ x,
        const float* __restrict__ w_off,
        const float* __restrict__ b_off) {
    __shared__ __align__(16) float xs[32][132];   // 528B rows: float4-legal
    __shared__ __align__(16) float ws[NOFF][32];

    int b = blockIdx.z, h = blockIdx.y, w0 = blockIdx.x * 32;
    int t = threadIdx.x, lane = t & 31, wid = t >> 5;

    const float* xp = x + (size_t)b*CIN*HW + h*W_ + w0;
    for (int i = t; i < 128*32; i += 256) {
        int c = i >> 5, px = i & 31;
        xs[px][c] = xp[(size_t)c*HW + px];
    }

    float acc[9];
    #pragma unroll
    for (int j = 0; j < 9; j++) acc[j] = 0.f;
    int obase = wid * 9;

    for (int cc = 0; cc < 4; cc++) {
        __syncthreads();
        for (int i = t; i < NOFF*32; i += 256) {
            int o = i >> 5, c2 = i & 31;
            ws[o][c2] = w_off[o*CIN + cc*32 + c2];
        }
        __syncthreads();
        #pragma unroll
        for (int c2 = 0; c2 < 32; c2 += 4) {
            float4 xv = *(const float4*)&xs[lane][cc*32 + c2];
            #pragma unroll
            for (int j = 0; j < 9; j++) {
                float4 wq = *(const float4*)&ws[obase + j][c2];
                acc[j] += xv.x*wq.x + xv.y*wq.y + xv.z*wq.z + xv.w*wq.w;
            }
        }
    }
    float* op = g_off + (size_t)b*NOFF*HW + h*W_ + w0 + lane;
    #pragma unroll
    for (int j = 0; j < 9; j++)
        op[(size_t)(obase + j)*HW] = acc[j] + b_off[obase + j];
}

// ---- NCHW gather (R11 form: lane=px -> coalesced corner rows) ----
__device__ __forceinline__ void gather_b(int gk, int h, int px, int cbase,
                                         const float* xb, const float* offp,
                                         __nv_bfloat16* BsD) {
    int g = gk / 9, kk = gk % 9;
    float offy = offp[(size_t)(gk*2 + 0)*HW];
    float offx = offp[(size_t)(gk*2 + 1)*HW];
    int ky = kk / 3, kx = kk % 3;
    float py  = offy + (float)(ky - 1) + (float)h;
    float pxf = offx + (float)(kx - 1) + (float)px;
    float y0f = floorf(py), x0f = floorf(pxf);
    float wy1 = py - y0f, wx1 = pxf - x0f;
    float wy0 = 1.f - wy1, wx0 = 1.f - wx1;
    int y0 = (int)y0f, x0 = (int)x0f;
    int y1 = y0 + 1, x1 = x0 + 1;
    bool vy0 = (y0 >= 0) & (y0 < H_);
    bool vy1 = (y1 >= 0) & (y1 < H_);
    bool vx0 = (x0 >= 0) & (x0 < W_);
    bool vx1 = (x1 >= 0) & (x1 < W_);
    float c00 = (vy0 & vx0) ? wy0*wx0 : 0.f;
    float c01 = (vy0 & vx1) ? wy0*wx1 : 0.f;
    float c10 = (vy1 & vx0) ? wy1*wx0 : 0.f;
    float c11 = (vy1 & vx1) ? wy1*wx1 : 0.f;
    int iy0 = min(max(y0, 0), H_-1), iy1 = min(max(y1, 0), H_-1);
    int ix0 = min(max(x0, 0), W_-1), ix1 = min(max(x1, 0), W_-1);
    int i00 = iy0*W_ + ix0, i01 = iy0*W_ + ix1;
    int i10 = iy1*W_ + ix0, i11 = iy1*W_ + ix1;

    const float* xg = xb + (size_t)g*CG*HW;
    #pragma unroll
    for (int j = 0; j < 16; j++) {
        int c = cbase + j;
        const float* xc = xg + (size_t)c*HW;
        float v = c00*xc[i00] + c01*xc[i01] + c10*xc[i10] + c11*xc[i11];
        __nv_bfloat16 hb = __float2bfloat16(v);
        __nv_bfloat16 lb = __float2bfloat16(v - __bfloat162float(hb));
        BsD[c*BSTR + px] = hb;          // s_hi rows [0,32)
        BsD[(32 + c)*BSTR + px] = lb;   // s_lo rows [32,64)
    }
}

// ---- async A staging via cp.async (no register round-trip) ----
__device__ __forceinline__ void stage_a_async(int gk, int t, __nv_bfloat16* AsD) {
    const char* src = (const char*)(g_wA + (size_t)gk * (128*KDIM));
    for (int i = t; i < 1536; i += 256) {
        int row = i / 12, q = i - row * 12;
        __pipeline_memcpy_async((char*)AsD + row * (ASTR*2) + q * 16,
                                src + i * 16, 16);
    }
}

// ============================================================
// Kernel 3: deformable conv + ReLU via WMMA bf16 split-MMA
// R11 schedule (best known) + cp.async double-buffered A:
// A(gk+1) prefetch issued at MMA(gk) start, completes during
// MMA+gather; A-stage leaves the serial path entirely.
// smem 70.7KB -> occ 2; B single-buffered (2 barriers/iter).
// ============================================================
__global__ __launch_bounds__(256, 2) void main_kernel(
        const float* __restrict__ x,
        float* __restrict__ out) {
    extern __shared__ __align__(16) char smem[];
    __nv_bfloat16* Asb[2] = {(__nv_bfloat16*)smem,
                             (__nv_bfloat16*)(smem + AS_BYTES)};
    __nv_bfloat16* Bs = (__nv_bfloat16*)(smem + 2*AS_BYTES);

    int t = threadIdx.x, lane = t & 31, wid = t >> 5;
    int h = blockIdx.x, b = blockIdx.y;

    // warp tiling
    int co_base = (wid & 1) * 64;     // co half
    int npx0 = (wid >> 1) * 32;       // 32-px strip

    // gather mapping
    int px = (wid & 3) * 32 + lane;   // 0..127
    int cbase = (wid >> 2) * 16;      // 0 or 16

    wmma::fragment<wmma::accumulator, 16, 16, 16, float> acc[4][2];
    #pragma unroll
    for (int mt = 0; mt < 4; mt++)
        #pragma unroll
        for (int nt = 0; nt < 2; nt++)
            wmma::fill_fragment(acc[mt][nt], 0.f);

    const float* xb = x + (size_t)b*CIN*HW;
    const float* offp = g_off + (size_t)b*NOFF*HW + h*W_ + px;

    // prologue: async A(0), gather B(0)
    stage_a_async(0, t, Asb[0]);
    __pipeline_commit();
    gather_b(0, h, px, cbase, xb, offp, Bs);
    __pipeline_wait_prior(0);
    __syncthreads();

    int p = 0;
    #pragma unroll 1
    for (int gk = 0; gk < NTILE; gk++) {
        // ---- prefetch A(gk+1) into spare buffer (completes under MMA+gather) ----
        if (gk + 1 < NTILE) {
            stage_a_async(gk + 1, t, Asb[p ^ 1]);
            __pipeline_commit();
        }

        // ---- 6 k16-steps on A[p], Bs; steps 4,5 reuse s_hi vs w_lo ----
        const __nv_bfloat16* As = Asb[p];
        #pragma unroll
        for (int kb = 0; kb < 6; kb++) {
            int krow = (kb & 3) * 16;      // 0,16,32,48,0,16
            wmma::fragment<wmma::matrix_b, 16, 16, 16, __nv_bfloat16, wmma::row_major> bf[2];
            #pragma unroll
            for (int nt = 0; nt < 2; nt++)
                wmma::load_matrix_sync(bf[nt], Bs + krow*BSTR + npx0 + nt*16, BSTR);
            #pragma unroll
            for (int mt = 0; mt < 4; mt++) {
                wmma::fragment<wmma::matrix_a, 16, 16, 16, __nv_bfloat16, wmma::row_major> af;
                wmma::load_matrix_sync(af, As + (co_base + mt*16)*ASTR + kb*16, ASTR);
                #pragma unroll
                for (int nt = 0; nt < 2; nt++)
                    wmma::mma_sync(acc[mt][nt], af, bf[nt], acc[mt][nt]);
            }
        }

        __syncthreads();                 // all warps done reading Bs
        if (gk + 1 < NTILE) {
            gather_b(gk + 1, h, px, cbase, xb, offp, Bs);
            __pipeline_wait_prior(0);    // this thread's A copies done
        }
        __syncthreads();                 // Bs + A[p^1] visible to all
        p ^= 1;
    }

    // ---- epilogue: fragment ReLU + direct wmma store to gmem ----
    float* outp = out + (size_t)b*COUT*HW + h*W_;
    #pragma unroll
    for (int mt = 0; mt < 4; mt++)
        #pragma unroll
        for (int nt = 0; nt < 2; nt++) {
            #pragma unroll
            for (int e = 0; e < acc[mt][nt].num_elements; e++)
                acc[mt][nt].x[e] = fmaxf(acc[mt][nt].x[e], 0.f);
            wmma::store_matrix_sync(outp + (size_t)(co_base + mt*16)*HW + npx0 + nt*16,
                                    acc[mt][nt], HW, wmma::mem_row_major);
        }
}

// ============================================================
extern "C" void kernel_launch(void* const* d_in, const int* in_sizes, int n_in,
                              void* d_out, int out_size) {
    const float* x     = (const float*)d_in[0];
    const float* w_off = (const float*)d_in[1];
    const float* b_off = (const float*)d_in[2];
    const float* w_def = (const float*)d_in[3];
    float* out = (float*)d_out;

    cudaFuncSetAttribute(main_kernel, cudaFuncAttributeMaxDynamicSharedMemorySize, SM_TOT);

    prep_w<<<(NTILE*128*KDIM + 255)/256, 256>>>(w_def);
    off_kernel<<<dim3(W_/32, H_, B_), 256>>>(x, w_off, b_off);
    main_kernel<<<dim3(H_, B_), 256, SM_TOT>>>(x, out);
}